// round 1
// baseline (speedup 1.0000x reference)
#include <cuda_runtime.h>
#include <cuda_bf16.h>
#include <math.h>

// Problem constants (fixed-shape problem)
#define D_LVLS 32
#define M_ATOMS 32768
#define NATM (1 + D_LVLS * M_ATOMS)

// Global scratch: per-node affine 3x4 HT, row-major:
//   [r00 r01 r02 tx] [r10 r11 r12 ty] [r20 r21 r22 tz]
// 12 floats = 48 bytes per node -> three aligned float4s.
__device__ float4 g_ht[NATM * 3];

// ---------------------------------------------------------------------------
// Local HT builders
// ---------------------------------------------------------------------------

// Bond HT: Rx(phi_p) @ Rz(theta) @ Tx(d) @ Rx(phi_c), closed form.
__device__ __forceinline__ void bond_ht(const float* dof, float r[9], float t[3]) {
    float cp, sp, ct, st, cc, sc;
    __sincosf(dof[0], &sp, &cp);
    __sincosf(dof[1], &st, &ct);
    __sincosf(dof[3], &sc, &cc);
    float d = dof[2];
    r[0] = ct;      r[1] = -st * cc;                 r[2] = st * sc;
    r[3] = cp * st; r[4] = cp * ct * cc - sp * sc;   r[5] = -cp * ct * sc - sp * cc;
    r[6] = sp * st; r[7] = sp * ct * cc + cp * sc;   r[8] = -sp * ct * sc + cp * cc;
    t[0] = ct * d;
    t[1] = cp * st * d;
    t[2] = sp * st * d;
}

// Euler ZYX rotation: Rz(z) @ Ry(y) @ Rx(x)
__device__ __forceinline__ void euler_zyx(float x, float y, float z, float r[9]) {
    float cx, sx, cy, sy, cz, sz;
    __sincosf(x, &sx, &cx);
    __sincosf(y, &sy, &cy);
    __sincosf(z, &sz, &cz);
    r[0] = cz * cy; r[1] = cz * sy * sx - sz * cx; r[2] = cz * sy * cx + sz * sx;
    r[3] = sz * cy; r[4] = sz * sy * sx + cz * cx; r[5] = sz * sy * cx - cz * sx;
    r[6] = -sy;     r[7] = cy * sx;                r[8] = cy * cx;
}

__device__ __forceinline__ void mat3_mul(const float a[9], const float b[9], float c[9]) {
#pragma unroll
    for (int i = 0; i < 3; i++)
#pragma unroll
        for (int j = 0; j < 3; j++)
            c[i * 3 + j] = a[i * 3 + 0] * b[0 * 3 + j]
                         + a[i * 3 + 1] * b[1 * 3 + j]
                         + a[i * 3 + 2] * b[2 * 3 + j];
}

// Jump HT: t = dof[0..2], R = (Rz(d5)Ry(d4)Rx(d3)) @ (Rz(d8)Ry(d7)Rx(d6))
__device__ __forceinline__ void jump_ht(const float* dof, float r[9], float t[3]) {
    float ra[9], rb[9];
    euler_zyx(dof[3], dof[4], dof[5], ra);
    euler_zyx(dof[6], dof[7], dof[8], rb);
    mat3_mul(ra, rb, r);
    t[0] = dof[0]; t[1] = dof[1]; t[2] = dof[2];
}

__device__ __forceinline__ void local_ht(const float* dof, int dtyp, float r[9], float t[3]) {
    if (dtyp == 0) jump_ht(dof, r, t);
    else           bond_ht(dof, r, t);
}

// ---------------------------------------------------------------------------
// Kernels
// ---------------------------------------------------------------------------

__global__ void root_kernel(const float* __restrict__ dofs,
                            const int* __restrict__ doftype,
                            float* __restrict__ out) {
    if (blockIdx.x == 0 && threadIdx.x == 0) {
        float dof[9];
#pragma unroll
        for (int k = 0; k < 9; k++) dof[k] = dofs[k];
        float r[9], t[3];
        local_ht(dof, doftype[0], r, t);
        g_ht[0] = make_float4(r[0], r[1], r[2], t[0]);
        g_ht[1] = make_float4(r[3], r[4], r[5], t[1]);
        g_ht[2] = make_float4(r[6], r[7], r[8], t[2]);
        out[0] = t[0]; out[1] = t[1]; out[2] = t[2];
    }
}

__global__ void level_kernel(const float* __restrict__ dofs,
                             const int* __restrict__ nodes,
                             const int* __restrict__ parents,
                             const int* __restrict__ doftype,
                             float* __restrict__ out) {
    int i = blockIdx.x * blockDim.x + threadIdx.x;
    if (i >= M_ATOMS) return;

    int node = nodes[i];
    int par  = parents[i];

    // Local HT from dofs
    const float* dof = dofs + (size_t)node * 9;
    float dl[9];
#pragma unroll
    for (int k = 0; k < 9; k++) dl[k] = dof[k];

    float rl[9], tl[3];
    local_ht(dl, doftype[node], rl, tl);

    // Parent global HT (random gather, contiguous 48B -> L2-friendly)
    float4 p0 = g_ht[(size_t)par * 3 + 0];
    float4 p1 = g_ht[(size_t)par * 3 + 1];
    float4 p2 = g_ht[(size_t)par * 3 + 2];

    float rp[9] = {p0.x, p0.y, p0.z,
                   p1.x, p1.y, p1.z,
                   p2.x, p2.y, p2.z};
    float tp[3] = {p0.w, p1.w, p2.w};

    // Compose: Rn = Rp @ Rl ; tn = Rp @ tl + tp
    float rn[9];
    mat3_mul(rp, rl, rn);
    float tn[3];
#pragma unroll
    for (int row = 0; row < 3; row++)
        tn[row] = rp[row * 3 + 0] * tl[0]
                + rp[row * 3 + 1] * tl[1]
                + rp[row * 3 + 2] * tl[2] + tp[row];

    // Store global HT
    g_ht[(size_t)node * 3 + 0] = make_float4(rn[0], rn[1], rn[2], tn[0]);
    g_ht[(size_t)node * 3 + 1] = make_float4(rn[3], rn[4], rn[5], tn[1]);
    g_ht[(size_t)node * 3 + 2] = make_float4(rn[6], rn[7], rn[8], tn[2]);

    // Output coordinate
    out[(size_t)node * 3 + 0] = tn[0];
    out[(size_t)node * 3 + 1] = tn[1];
    out[(size_t)node * 3 + 2] = tn[2];
}

// ---------------------------------------------------------------------------
// Launch
// ---------------------------------------------------------------------------

extern "C" void kernel_launch(void* const* d_in, const int* in_sizes, int n_in,
                              void* d_out, int out_size) {
    const float* dofs         = (const float*)d_in[0];
    const int*   level_nodes   = (const int*)d_in[1];
    const int*   level_parents = (const int*)d_in[2];
    const int*   doftype       = (const int*)d_in[3];
    float*       out           = (float*)d_out;

    root_kernel<<<1, 32>>>(dofs, doftype, out);

    const int threads = 128;
    const int blocks = (M_ATOMS + threads - 1) / threads;
    for (int l = 0; l < D_LVLS; l++) {
        level_kernel<<<blocks, threads>>>(dofs,
                                          level_nodes + (size_t)l * M_ATOMS,
                                          level_parents + (size_t)l * M_ATOMS,
                                          doftype, out);
    }
}